// round 8
// baseline (speedup 1.0000x reference)
#include <cuda_runtime.h>

#define NN 100000
#define EE 1600000
#define EPSI 1e-12f
#define SCAN_B 512
#define NBLK ((NN + SCAN_B - 1) / SCAN_B)   // 196

// ---------------- scratch (device globals; no allocation allowed) ----------------
__device__ float4 g_h4[NN * 16];        // h1 (N x 64); later h2b (N x 32)
__device__ float4 g_t4[NN * 8];         // h2pre (N x 32)
__device__ float  g_degO[3 * NN];
__device__ float  g_sO[3 * NN];         // rsqrt(degO)
__device__ int    g_cnt[3 * NN];
__device__ int    g_ptr[3 * (NN + 1)];
__device__ int    g_cur[3 * NN];
__device__ int    g_psum[3 * NBLK];
__device__ int    g_psumx[3 * NBLK];
__device__ int2   g_csr[3 * EE];        // (src, __float_as_int(w*rsqrt(degO[src]))) by dst

// ---------------- zero (split so deg3 lands at capture slot 3) ----------------
__global__ void k_zero_degO() {
    int i = blockIdx.x * blockDim.x + threadIdx.x;
    if (i < 3 * NN) g_degO[i] = 0.f;
}
__global__ void k_zero_cnt() {
    int i = blockIdx.x * blockDim.x + threadIdx.x;
    if (i < 3 * NN) g_cnt[i] = 0;
}

// ---------------- degrees + dst histogram, 3 graphs, 4 edges/thread ----------------
__global__ void k_deg3(const int* __restrict__ s1, const int* __restrict__ d1, const float* __restrict__ w1,
                       const int* __restrict__ s2, const int* __restrict__ d2, const float* __restrict__ w2,
                       const int* __restrict__ s3, const int* __restrict__ d3, const float* __restrict__ w3) {
    int g = blockIdx.y;
    const int*   src = (g == 0) ? s1 : (g == 1) ? s2 : s3;
    const int*   dst = (g == 0) ? d1 : (g == 1) ? d2 : d3;
    const float* w   = (g == 0) ? w1 : (g == 1) ? w2 : w3;
    int i = blockIdx.x * blockDim.x + threadIdx.x;
    int e = i * 4;
    if (e + 3 < EE) {
        int4   s4 = ((const int4*)src)[i];
        int4   d4 = ((const int4*)dst)[i];
        float4 w4 = ((const float4*)w)[i];
        int base = g * NN;
        atomicAdd(&g_degO[base + s4.x], w4.x);
        atomicAdd(&g_degO[base + s4.y], w4.y);
        atomicAdd(&g_degO[base + s4.z], w4.z);
        atomicAdd(&g_degO[base + s4.w], w4.w);
        atomicAdd(&g_cnt[base + d4.x], 1);
        atomicAdd(&g_cnt[base + d4.y], 1);
        atomicAdd(&g_cnt[base + d4.z], 1);
        atomicAdd(&g_cnt[base + d4.w], 1);
    }
}

// ---------------- scan1 + fused sO = rsqrt(degO) ----------------
__global__ void k_scan1rsq() {
    __shared__ int s[SCAN_B];
    int g = blockIdx.y;
    int t = threadIdx.x;
    int i = blockIdx.x * SCAN_B + t;
    if (i < NN) g_sO[g * NN + i] = rsqrtf(fmaxf(g_degO[g * NN + i], EPSI));
    s[t] = (i < NN) ? g_cnt[g * NN + i] : 0;
    __syncthreads();
    for (int off = SCAN_B / 2; off > 0; off >>= 1) {
        if (t < off) s[t] += s[t + off];
        __syncthreads();
    }
    if (t == 0) g_psum[g * NBLK + blockIdx.x] = s[0];
}

__global__ void k_scan2() {
    __shared__ int s[256];
    int g = blockIdx.y;
    int t = threadIdx.x;
    int v = (t < NBLK) ? g_psum[g * NBLK + t] : 0;
    s[t] = v;
    __syncthreads();
    for (int off = 1; off < 256; off <<= 1) {
        int x = (t >= off) ? s[t - off] : 0;
        __syncthreads();
        s[t] += x;
        __syncthreads();
    }
    if (t < NBLK) g_psumx[g * NBLK + t] = s[t] - v;   // exclusive
}

__global__ void k_scan3() {
    __shared__ int s[SCAN_B];
    int g = blockIdx.y;
    int t = threadIdx.x;
    int i = blockIdx.x * SCAN_B + t;
    int v = (i < NN) ? g_cnt[g * NN + i] : 0;
    s[t] = v;
    __syncthreads();
    for (int off = 1; off < SCAN_B; off <<= 1) {
        int x = (t >= off) ? s[t - off] : 0;
        __syncthreads();
        s[t] += x;
        __syncthreads();
    }
    int excl = s[t] - v + g_psumx[g * NBLK + blockIdx.x];
    if (i < NN) { g_ptr[g * (NN + 1) + i] = excl; g_cur[g * NN + i] = excl; }
    if (i == NN - 1) g_ptr[g * (NN + 1) + NN] = excl + v;   // == EE
}

// ---------------- fill CSR, 4 edges/thread ----------------
__global__ void k_fill3(const int* __restrict__ s1, const int* __restrict__ d1, const float* __restrict__ w1,
                        const int* __restrict__ s2, const int* __restrict__ d2, const float* __restrict__ w2,
                        const int* __restrict__ s3, const int* __restrict__ d3, const float* __restrict__ w3) {
    int g = blockIdx.y;
    const int*   src = (g == 0) ? s1 : (g == 1) ? s2 : s3;
    const int*   dst = (g == 0) ? d1 : (g == 1) ? d2 : d3;
    const float* w   = (g == 0) ? w1 : (g == 1) ? w2 : w3;
    int i = blockIdx.x * blockDim.x + threadIdx.x;
    int e = i * 4;
    if (e + 3 < EE) {
        int4   s4 = ((const int4*)src)[i];
        int4   d4 = ((const int4*)dst)[i];
        float4 w4 = ((const float4*)w)[i];
        const float* sO = g_sO + g * NN;
        int* cur = g_cur + g * NN;
        int2* csr = g_csr + g * EE;
        float ws0 = w4.x * sO[s4.x];
        float ws1 = w4.y * sO[s4.y];
        float ws2 = w4.z * sO[s4.z];
        float ws3 = w4.w * sO[s4.w];
        int p0 = atomicAdd(&cur[d4.x], 1);
        int p1 = atomicAdd(&cur[d4.y], 1);
        int p2 = atomicAdd(&cur[d4.z], 1);
        int p3 = atomicAdd(&cur[d4.w], 1);
        csr[p0] = make_int2(s4.x, __float_as_int(ws0));
        csr[p1] = make_int2(s4.y, __float_as_int(ws1));
        csr[p2] = make_int2(s4.z, __float_as_int(ws2));
        csr[p3] = make_int2(s4.w, __float_as_int(ws3));
    }
}

// ---------------- mm1: h1 = x @ W1  (N x 128)@(128 x 64) -> g_h4 ----------------
__global__ void k_mm1(const float* __restrict__ x, const float* __restrict__ W1) {
    __shared__ float ws[128 * 64];   // 32 KB
    __shared__ float xs[32 * 128];   // 16 KB
    int t = threadIdx.x;
    {
        const float4* W14 = (const float4*)W1;
        float4* ws4w = (float4*)ws;
        #pragma unroll
        for (int i = 0; i < 8; i++) ws4w[t + i * 256] = W14[t + i * 256];
    }
    const float4* ws4 = (const float4*)ws;
    int jg = t & 15;
    int r  = t >> 4;
    int row0 = blockIdx.x * 32;      // grid = 3125, exact
    {
        const float4* x4 = (const float4*)x;
        float4* xs4 = (float4*)xs;
        #pragma unroll
        for (int i = 0; i < 4; i++) {
            int idx = t + i * 256;
            xs4[idx] = x4[row0 * 32 + idx];
        }
    }
    __syncthreads();
    float4 a0 = make_float4(0.f, 0.f, 0.f, 0.f);
    float4 a1 = make_float4(0.f, 0.f, 0.f, 0.f);
    #pragma unroll 4
    for (int k = 0; k < 128; k++) {
        float  x0 = xs[r * 128 + k];
        float  x1 = xs[(r + 16) * 128 + k];
        float4 wv = ws4[k * 16 + jg];
        a0.x += x0 * wv.x; a0.y += x0 * wv.y; a0.z += x0 * wv.z; a0.w += x0 * wv.w;
        a1.x += x1 * wv.x; a1.y += x1 * wv.y; a1.z += x1 * wv.z; a1.w += x1 * wv.w;
    }
    g_h4[(row0 + r) * 16 + jg]      = a0;
    g_h4[(row0 + r + 16) * 16 + jg] = a1;
}

// ---------------- fused pull64 (g=0) + mm2: h2pre = (agg1/dw + b1) @ W2 -> g_t4 ------
// 512 threads = 16 warps; warp w owns row blockIdx.x*16 + w.
// Lane = ep*16 + fl: ep in {0,1} edge-parallel, fl in 0..15 feature float4.
__global__ void __launch_bounds__(512) k_pull64mm2(const float* __restrict__ b1,
                                                   const float* __restrict__ W2) {
    __shared__ float hs[16 * 64];    // 4 KB block tile of h1b
    __shared__ float ws[64 * 32];    // 8 KB W2
    int t = threadIdx.x;
    ((float4*)ws)[t] = ((const float4*)W2)[t];   // 512 float4 = 2048 floats
    int w  = t >> 5;
    int ln = t & 31;
    int ep = ln >> 4;                // 0..1
    int fl = ln & 15;                // 0..15
    int row = blockIdx.x * 16 + w;   // exact: 6250*16 = 100000
    int beg = g_ptr[row], end = g_ptr[row + 1];
    float4 acc = make_float4(0.f, 0.f, 0.f, 0.f);
    float dw = 0.f;
    #pragma unroll 8
    for (int j = beg + ep; j < end; j += 2) {
        int2 e = __ldcs(&g_csr[j]);
        float n = __int_as_float(e.y);
        float4 h = g_h4[e.x * 16 + fl];
        acc.x += h.x * n; acc.y += h.y * n;
        acc.z += h.z * n; acc.w += h.w * n;
        dw += n;
    }
    // reduce across ep (xor 16)
    acc.x += __shfl_xor_sync(0xffffffffu, acc.x, 16);
    acc.y += __shfl_xor_sync(0xffffffffu, acc.y, 16);
    acc.z += __shfl_xor_sync(0xffffffffu, acc.z, 16);
    acc.w += __shfl_xor_sync(0xffffffffu, acc.w, 16);
    dw    += __shfl_xor_sync(0xffffffffu, dw, 16);
    if (ep == 0) {
        float inv = 1.f / fmaxf(dw, EPSI);
        float4 bb = ((const float4*)b1)[fl];
        ((float4*)hs)[w * 16 + fl] = make_float4(acc.x * inv + bb.x, acc.y * inv + bb.y,
                                                 acc.z * inv + bb.z, acc.w * inv + bb.w);
    }
    __syncthreads();
    // mm2: 16x64 @ 64x32 -> 16x32; thread -> (r = t>>5, c = t&31)
    int r = t >> 5, c = t & 31;
    float s = 0.f;
    #pragma unroll
    for (int k = 0; k < 64; k++)
        s += hs[r * 64 + k] * ws[k * 32 + c];
    ((float*)g_t4)[(blockIdx.x * 16 + r) * 32 + c] = s;
}

// ---------------- pull32 layer 2 (g=1): h2b = agg2/dw + b2 : g_t4 -> g_h4 -----------
__global__ void __launch_bounds__(512) k_pull32L2(const float* __restrict__ b2) {
    int t = threadIdx.x;
    int w  = t >> 5;
    int ln = t & 31;
    int ep = ln >> 3;                // 0..3
    int fl = ln & 7;                 // 0..7
    int row = blockIdx.x * 16 + w;
    const int2* csr = g_csr + 1 * EE;
    int beg = g_ptr[1 * (NN + 1) + row], end = g_ptr[1 * (NN + 1) + row + 1];
    float4 acc = make_float4(0.f, 0.f, 0.f, 0.f);
    float dw = 0.f;
    #pragma unroll 4
    for (int j = beg + ep; j < end; j += 4) {
        int2 e = __ldcs(&csr[j]);
        float n = __int_as_float(e.y);
        float4 h = g_t4[e.x * 8 + fl];
        acc.x += h.x * n; acc.y += h.y * n;
        acc.z += h.z * n; acc.w += h.w * n;
        dw += n;
    }
    acc.x += __shfl_xor_sync(0xffffffffu, acc.x, 8);
    acc.y += __shfl_xor_sync(0xffffffffu, acc.y, 8);
    acc.z += __shfl_xor_sync(0xffffffffu, acc.z, 8);
    acc.w += __shfl_xor_sync(0xffffffffu, acc.w, 8);
    dw    += __shfl_xor_sync(0xffffffffu, dw, 8);
    acc.x += __shfl_xor_sync(0xffffffffu, acc.x, 16);
    acc.y += __shfl_xor_sync(0xffffffffu, acc.y, 16);
    acc.z += __shfl_xor_sync(0xffffffffu, acc.z, 16);
    acc.w += __shfl_xor_sync(0xffffffffu, acc.w, 16);
    dw    += __shfl_xor_sync(0xffffffffu, dw, 16);
    if (ep == 0) {
        float inv = 1.f / fmaxf(dw, EPSI);
        float4 bb = ((const float4*)b2)[fl];
        g_h4[row * 8 + fl] = make_float4(acc.x * inv + bb.x, acc.y * inv + bb.y,
                                         acc.z * inv + bb.z, acc.w * inv + bb.w);
    }
}

// ---------------- fused pull32 layer 3 (g=2) + fin3: out = (agg3/dw) @ W3 + b3 ------
__global__ void __launch_bounds__(512) k_pull32fin3(const float* __restrict__ W3,
                                                    const float* __restrict__ b3,
                                                    float* __restrict__ out) {
    __shared__ float hs[16 * 32];    // 2 KB block tile of aggnorm3
    __shared__ float ws[32 * 32];    // 4 KB W3
    int t = threadIdx.x;
    if (t < 256) ((float4*)ws)[t] = ((const float4*)W3)[t];   // 256 float4 = 1024 floats
    int w  = t >> 5;
    int ln = t & 31;
    int ep = ln >> 3;
    int fl = ln & 7;
    int row = blockIdx.x * 16 + w;
    const int2* csr = g_csr + 2 * EE;
    int beg = g_ptr[2 * (NN + 1) + row], end = g_ptr[2 * (NN + 1) + row + 1];
    float4 acc = make_float4(0.f, 0.f, 0.f, 0.f);
    float dw = 0.f;
    #pragma unroll 4
    for (int j = beg + ep; j < end; j += 4) {
        int2 e = __ldcs(&csr[j]);
        float n = __int_as_float(e.y);
        float4 h = g_h4[e.x * 8 + fl];
        acc.x += h.x * n; acc.y += h.y * n;
        acc.z += h.z * n; acc.w += h.w * n;
        dw += n;
    }
    acc.x += __shfl_xor_sync(0xffffffffu, acc.x, 8);
    acc.y += __shfl_xor_sync(0xffffffffu, acc.y, 8);
    acc.z += __shfl_xor_sync(0xffffffffu, acc.z, 8);
    acc.w += __shfl_xor_sync(0xffffffffu, acc.w, 8);
    dw    += __shfl_xor_sync(0xffffffffu, dw, 8);
    acc.x += __shfl_xor_sync(0xffffffffu, acc.x, 16);
    acc.y += __shfl_xor_sync(0xffffffffu, acc.y, 16);
    acc.z += __shfl_xor_sync(0xffffffffu, acc.z, 16);
    acc.w += __shfl_xor_sync(0xffffffffu, acc.w, 16);
    dw    += __shfl_xor_sync(0xffffffffu, dw, 16);
    if (ep == 0) {
        float inv = 1.f / fmaxf(dw, EPSI);
        ((float4*)hs)[w * 8 + fl] = make_float4(acc.x * inv, acc.y * inv,
                                                acc.z * inv, acc.w * inv);
    }
    __syncthreads();
    // fin3: 16x32 @ 32x32 + b3
    int r = t >> 5, c = t & 31;
    float s = 0.f;
    #pragma unroll
    for (int k = 0; k < 32; k++)
        s += hs[r * 32 + k] * ws[k * 32 + c];
    out[(blockIdx.x * 16 + r) * 32 + c] = s + b3[c];
}

// ---------------- launch ----------------
extern "C" void kernel_launch(void* const* d_in, const int* in_sizes, int n_in,
                              void* d_out, int out_size) {
    const float* x    = (const float*)d_in[0];
    const int*   src1 = (const int*)  d_in[1];
    const int*   dst1 = (const int*)  d_in[2];
    const float* w1   = (const float*)d_in[3];
    const int*   src2 = (const int*)  d_in[4];
    const int*   dst2 = (const int*)  d_in[5];
    const float* w2   = (const float*)d_in[6];
    const int*   src3 = (const int*)  d_in[7];
    const int*   dst3 = (const int*)  d_in[8];
    const float* w3   = (const float*)d_in[9];
    const float* W1   = (const float*)d_in[10];
    const float* b1   = (const float*)d_in[11];
    const float* W2   = (const float*)d_in[12];
    const float* b2   = (const float*)d_in[13];
    const float* W3   = (const float*)d_in[14];
    const float* b3   = (const float*)d_in[15];
    float* out = (float*)d_out;

    const int TB = 256;
    dim3 gE3v((EE / 4 + TB - 1) / TB, 3);        // 1563 x 3 blocks, 4 edges/thread

    // slots 0..3 arranged so ncu captures k_deg3 (launch index 3)
    k_zero_degO<<<(3 * NN + TB - 1) / TB, TB>>>();       // 0
    k_zero_cnt<<<(3 * NN + TB - 1) / TB, TB>>>();        // 1
    k_mm1<<<NN / 32, 256>>>(x, W1);                      // 2 (independent)
    k_deg3<<<gE3v, TB>>>(src1, dst1, w1, src2, dst2, w2, src3, dst3, w3);   // 3
    k_scan1rsq<<<dim3(NBLK, 3), SCAN_B>>>();             // 4 (scan + fused rsqrt)
    k_scan2<<<dim3(1, 3), 256>>>();                      // 5
    k_scan3<<<dim3(NBLK, 3), SCAN_B>>>();                // 6
    k_fill3<<<gE3v, TB>>>(src1, dst1, w1, src2, dst2, w2, src3, dst3, w3);  // 7

    // Dependent compute chain (fused)
    k_pull64mm2<<<NN / 16, 512>>>(b1, W2);       // g=0: g_h4 -> g_t4 (h2pre)
    k_pull32L2<<<NN / 16, 512>>>(b2);            // g=1: g_t4 -> g_h4 (h2b)
    k_pull32fin3<<<NN / 16, 512>>>(W3, b3, out); // g=2: g_h4 -> out
}

// round 9
// speedup vs baseline: 1.0977x; 1.0977x over previous
#include <cuda_runtime.h>

#define NN 100000
#define EE 1600000
#define EPSI 1e-12f
#define CAP 64                       // padded bucket capacity per dst node

// ---------------- scratch (device globals; no allocation allowed) ----------------
__device__ float4 g_h4[NN * 16];     // h1 (N x 64); later h2b (N x 32)
__device__ float4 g_t4[NN * 8];      // h2pre (N x 32)
__device__ float  g_degO[3 * NN];
__device__ float  g_sO[3 * NN];      // rsqrt(degO)
__device__ int    g_cur[3 * NN];     // bucket cursors == in-degree counts after fill
__device__ int2   g_csr[3 * NN * CAP];   // (src, __float_as_int(w)) padded buckets by dst

// ---------------- zero (split for capture-slot alignment) ----------------
__global__ void k_zero_degO() {
    int i = blockIdx.x * blockDim.x + threadIdx.x;
    if (i < 3 * NN) g_degO[i] = 0.f;
}
__global__ void k_zero_cur() {
    int i = blockIdx.x * blockDim.x + threadIdx.x;
    if (i < 3 * NN) g_cur[i] = 0;
}

// ---------------- one-pass build: degO atomic + bucket scatter, 3 graphs ----------------
__global__ void k_fill3(const int* __restrict__ s1, const int* __restrict__ d1, const float* __restrict__ w1,
                        const int* __restrict__ s2, const int* __restrict__ d2, const float* __restrict__ w2,
                        const int* __restrict__ s3, const int* __restrict__ d3, const float* __restrict__ w3) {
    int g = blockIdx.y;
    const int*   src = (g == 0) ? s1 : (g == 1) ? s2 : s3;
    const int*   dst = (g == 0) ? d1 : (g == 1) ? d2 : d3;
    const float* w   = (g == 0) ? w1 : (g == 1) ? w2 : w3;
    int e = blockIdx.x * blockDim.x + threadIdx.x;
    if (e < EE) {
        int s = src[e], d = dst[e];
        float wv = w[e];
        atomicAdd(&g_degO[g * NN + s], wv);
        int pos = atomicAdd(&g_cur[g * NN + d], 1);
        g_csr[(g * NN + d) * CAP + pos] = make_int2(s, __float_as_int(wv));
    }
}

// ---------------- sO = rsqrt(degO) ----------------
__global__ void k_rsq3() {
    int i = blockIdx.x * blockDim.x + threadIdx.x;
    if (i < 3 * NN) g_sO[i] = rsqrtf(fmaxf(g_degO[i], EPSI));
}

// ---------------- mm1: h1 = x @ W1  (N x 128)@(128 x 64) -> g_h4 ----------------
__global__ void k_mm1(const float* __restrict__ x, const float* __restrict__ W1) {
    __shared__ float ws[128 * 64];   // 32 KB
    __shared__ float xs[32 * 128];   // 16 KB
    int t = threadIdx.x;
    {
        const float4* W14 = (const float4*)W1;
        float4* ws4w = (float4*)ws;
        #pragma unroll
        for (int i = 0; i < 8; i++) ws4w[t + i * 256] = W14[t + i * 256];
    }
    const float4* ws4 = (const float4*)ws;
    int jg = t & 15;
    int r  = t >> 4;
    int row0 = blockIdx.x * 32;      // grid = 3125, exact
    {
        const float4* x4 = (const float4*)x;
        float4* xs4 = (float4*)xs;
        #pragma unroll
        for (int i = 0; i < 4; i++) {
            int idx = t + i * 256;
            xs4[idx] = x4[row0 * 32 + idx];
        }
    }
    __syncthreads();
    float4 a0 = make_float4(0.f, 0.f, 0.f, 0.f);
    float4 a1 = make_float4(0.f, 0.f, 0.f, 0.f);
    #pragma unroll 4
    for (int k = 0; k < 128; k++) {
        float  x0 = xs[r * 128 + k];
        float  x1 = xs[(r + 16) * 128 + k];
        float4 wv = ws4[k * 16 + jg];
        a0.x += x0 * wv.x; a0.y += x0 * wv.y; a0.z += x0 * wv.z; a0.w += x0 * wv.w;
        a1.x += x1 * wv.x; a1.y += x1 * wv.y; a1.z += x1 * wv.z; a1.w += x1 * wv.w;
    }
    g_h4[(row0 + r) * 16 + jg]      = a0;
    g_h4[(row0 + r + 16) * 16 + jg] = a1;
}

// ---------------- fused pull64 (g=0) + mm2: h2pre = (agg1/dw + b1) @ W2 -> g_t4 ------
// 512 threads = 16 warps; warp w owns row blockIdx.x*16 + w.
// Lane = ep*16 + fl: ep in {0,1} edge-parallel, fl in 0..15 feature float4.
__global__ void __launch_bounds__(512) k_pull64mm2(const float* __restrict__ b1,
                                                   const float* __restrict__ W2) {
    __shared__ float hs[16 * 64];    // 4 KB block tile of h1b
    __shared__ float ws[64 * 32];    // 8 KB W2
    int t = threadIdx.x;
    ((float4*)ws)[t] = ((const float4*)W2)[t];   // 512 float4 = 2048 floats
    int w  = t >> 5;
    int ln = t & 31;
    int ep = ln >> 4;                // 0..1
    int fl = ln & 15;                // 0..15
    int row = blockIdx.x * 16 + w;   // exact: 6250*16 = 100000
    int cnt = g_cur[row];
    int base = row * CAP;
    float4 acc = make_float4(0.f, 0.f, 0.f, 0.f);
    float dw = 0.f;
    #pragma unroll 4
    for (int j = ep; j < cnt; j += 2) {
        int2 e = __ldcs(&g_csr[base + j]);
        float n = __int_as_float(e.y) * __ldg(&g_sO[e.x]);
        float4 h = g_h4[e.x * 16 + fl];
        acc.x += h.x * n; acc.y += h.y * n;
        acc.z += h.z * n; acc.w += h.w * n;
        dw += n;
    }
    // reduce across ep (xor 16)
    acc.x += __shfl_xor_sync(0xffffffffu, acc.x, 16);
    acc.y += __shfl_xor_sync(0xffffffffu, acc.y, 16);
    acc.z += __shfl_xor_sync(0xffffffffu, acc.z, 16);
    acc.w += __shfl_xor_sync(0xffffffffu, acc.w, 16);
    dw    += __shfl_xor_sync(0xffffffffu, dw, 16);
    if (ep == 0) {
        float inv = 1.f / fmaxf(dw, EPSI);
        float4 bb = ((const float4*)b1)[fl];
        ((float4*)hs)[w * 16 + fl] = make_float4(acc.x * inv + bb.x, acc.y * inv + bb.y,
                                                 acc.z * inv + bb.z, acc.w * inv + bb.w);
    }
    __syncthreads();
    // mm2: 16x64 @ 64x32 -> 16x32; thread -> (r = t>>5, c = t&31)
    int r = t >> 5, c = t & 31;
    float s = 0.f;
    #pragma unroll
    for (int k = 0; k < 64; k++)
        s += hs[r * 64 + k] * ws[k * 32 + c];
    ((float*)g_t4)[(blockIdx.x * 16 + r) * 32 + c] = s;
}

// ---------------- pull32 layer 2 (g=1): h2b = agg2/dw + b2 : g_t4 -> g_h4 -----------
__global__ void __launch_bounds__(512) k_pull32L2(const float* __restrict__ b2) {
    int t = threadIdx.x;
    int w  = t >> 5;
    int ln = t & 31;
    int ep = ln >> 3;                // 0..3
    int fl = ln & 7;                 // 0..7
    int row = blockIdx.x * 16 + w;
    const float* sO = g_sO + NN;
    int cnt = g_cur[NN + row];
    int base = (NN + row) * CAP;
    float4 acc = make_float4(0.f, 0.f, 0.f, 0.f);
    float dw = 0.f;
    #pragma unroll 4
    for (int j = ep; j < cnt; j += 4) {
        int2 e = __ldcs(&g_csr[base + j]);
        float n = __int_as_float(e.y) * __ldg(&sO[e.x]);
        float4 h = g_t4[e.x * 8 + fl];
        acc.x += h.x * n; acc.y += h.y * n;
        acc.z += h.z * n; acc.w += h.w * n;
        dw += n;
    }
    acc.x += __shfl_xor_sync(0xffffffffu, acc.x, 8);
    acc.y += __shfl_xor_sync(0xffffffffu, acc.y, 8);
    acc.z += __shfl_xor_sync(0xffffffffu, acc.z, 8);
    acc.w += __shfl_xor_sync(0xffffffffu, acc.w, 8);
    dw    += __shfl_xor_sync(0xffffffffu, dw, 8);
    acc.x += __shfl_xor_sync(0xffffffffu, acc.x, 16);
    acc.y += __shfl_xor_sync(0xffffffffu, acc.y, 16);
    acc.z += __shfl_xor_sync(0xffffffffu, acc.z, 16);
    acc.w += __shfl_xor_sync(0xffffffffu, acc.w, 16);
    dw    += __shfl_xor_sync(0xffffffffu, dw, 16);
    if (ep == 0) {
        float inv = 1.f / fmaxf(dw, EPSI);
        float4 bb = ((const float4*)b2)[fl];
        g_h4[row * 8 + fl] = make_float4(acc.x * inv + bb.x, acc.y * inv + bb.y,
                                         acc.z * inv + bb.z, acc.w * inv + bb.w);
    }
}

// ---------------- fused pull32 layer 3 (g=2) + fin3: out = (agg3/dw) @ W3 + b3 ------
__global__ void __launch_bounds__(512) k_pull32fin3(const float* __restrict__ W3,
                                                    const float* __restrict__ b3,
                                                    float* __restrict__ out) {
    __shared__ float hs[16 * 32];    // 2 KB block tile of aggnorm3
    __shared__ float ws[32 * 32];    // 4 KB W3
    int t = threadIdx.x;
    if (t < 256) ((float4*)ws)[t] = ((const float4*)W3)[t];   // 256 float4 = 1024 floats
    int w  = t >> 5;
    int ln = t & 31;
    int ep = ln >> 3;
    int fl = ln & 7;
    int row = blockIdx.x * 16 + w;
    const float* sO = g_sO + 2 * NN;
    int cnt = g_cur[2 * NN + row];
    int base = (2 * NN + row) * CAP;
    float4 acc = make_float4(0.f, 0.f, 0.f, 0.f);
    float dw = 0.f;
    #pragma unroll 4
    for (int j = ep; j < cnt; j += 4) {
        int2 e = __ldcs(&g_csr[base + j]);
        float n = __int_as_float(e.y) * __ldg(&sO[e.x]);
        float4 h = g_h4[e.x * 8 + fl];
        acc.x += h.x * n; acc.y += h.y * n;
        acc.z += h.z * n; acc.w += h.w * n;
        dw += n;
    }
    acc.x += __shfl_xor_sync(0xffffffffu, acc.x, 8);
    acc.y += __shfl_xor_sync(0xffffffffu, acc.y, 8);
    acc.z += __shfl_xor_sync(0xffffffffu, acc.z, 8);
    acc.w += __shfl_xor_sync(0xffffffffu, acc.w, 8);
    dw    += __shfl_xor_sync(0xffffffffu, dw, 8);
    acc.x += __shfl_xor_sync(0xffffffffu, acc.x, 16);
    acc.y += __shfl_xor_sync(0xffffffffu, acc.y, 16);
    acc.z += __shfl_xor_sync(0xffffffffu, acc.z, 16);
    acc.w += __shfl_xor_sync(0xffffffffu, acc.w, 16);
    dw    += __shfl_xor_sync(0xffffffffu, dw, 16);
    if (ep == 0) {
        float inv = 1.f / fmaxf(dw, EPSI);
        ((float4*)hs)[w * 8 + fl] = make_float4(acc.x * inv, acc.y * inv,
                                                acc.z * inv, acc.w * inv);
    }
    __syncthreads();
    // fin3: 16x32 @ 32x32 + b3
    int r = t >> 5, c = t & 31;
    float s = 0.f;
    #pragma unroll
    for (int k = 0; k < 32; k++)
        s += hs[r * 32 + k] * ws[k * 32 + c];
    out[(blockIdx.x * 16 + r) * 32 + c] = s + b3[c];
}

// ---------------- launch ----------------
extern "C" void kernel_launch(void* const* d_in, const int* in_sizes, int n_in,
                              void* d_out, int out_size) {
    const float* x    = (const float*)d_in[0];
    const int*   src1 = (const int*)  d_in[1];
    const int*   dst1 = (const int*)  d_in[2];
    const float* w1   = (const float*)d_in[3];
    const int*   src2 = (const int*)  d_in[4];
    const int*   dst2 = (const int*)  d_in[5];
    const float* w2   = (const float*)d_in[6];
    const int*   src3 = (const int*)  d_in[7];
    const int*   dst3 = (const int*)  d_in[8];
    const float* w3   = (const float*)d_in[9];
    const float* W1   = (const float*)d_in[10];
    const float* b1   = (const float*)d_in[11];
    const float* W2   = (const float*)d_in[12];
    const float* b2   = (const float*)d_in[13];
    const float* W3   = (const float*)d_in[14];
    const float* b3   = (const float*)d_in[15];
    float* out = (float*)d_out;

    const int TB = 256;
    dim3 gE3((EE + TB - 1) / TB, 3);             // 6250 x 3 blocks, 1 edge/thread

    // slots 0..3 arranged so ncu captures k_fill3 (launch index 3)
    k_zero_degO<<<(3 * NN + TB - 1) / TB, TB>>>();       // 0
    k_zero_cur<<<(3 * NN + TB - 1) / TB, TB>>>();        // 1
    k_mm1<<<NN / 32, 256>>>(x, W1);                      // 2 (independent)
    k_fill3<<<gE3, TB>>>(src1, dst1, w1, src2, dst2, w2, src3, dst3, w3);   // 3
    k_rsq3<<<(3 * NN + TB - 1) / TB, TB>>>();            // 4

    // Dependent compute chain (fused)
    k_pull64mm2<<<NN / 16, 512>>>(b1, W2);       // g=0: g_h4 -> g_t4 (h2pre)
    k_pull32L2<<<NN / 16, 512>>>(b2);            // g=1: g_t4 -> g_h4 (h2b)
    k_pull32fin3<<<NN / 16, 512>>>(W3, b3, out); // g=2: g_h4 -> out
}

// round 10
// speedup vs baseline: 1.0978x; 1.0001x over previous
#include <cuda_runtime.h>

#define NN 100000
#define EE 1600000
#define EPSI 1e-12f
#define CAP 64                       // padded bucket capacity per dst node

// ---------------- scratch (device globals; no allocation allowed) ----------------
__device__ float4 g_h4[NN * 16];     // h1 (N x 64); later h2b (N x 32)
__device__ float4 g_t4[NN * 8];      // h2pre (N x 32)
__device__ float  g_degO[3 * NN];
__device__ int    g_cur[3 * NN];     // bucket cursors == in-degree counts after fill
__device__ int2   g_csr[3 * NN * CAP];   // (src, __float_as_int(w)) padded buckets by dst

// ---------------- zero: degO + cur ----------------
__global__ void k_zero() {
    int i = blockIdx.x * blockDim.x + threadIdx.x;
    if (i < 3 * NN) { g_degO[i] = 0.f; g_cur[i] = 0; }
}

// ---------------- one-pass build: degO atomic + bucket scatter, 3 graphs ----------------
__global__ void k_fill3(const int* __restrict__ s1, const int* __restrict__ d1, const float* __restrict__ w1,
                        const int* __restrict__ s2, const int* __restrict__ d2, const float* __restrict__ w2,
                        const int* __restrict__ s3, const int* __restrict__ d3, const float* __restrict__ w3) {
    int g = blockIdx.y;
    const int*   src = (g == 0) ? s1 : (g == 1) ? s2 : s3;
    const int*   dst = (g == 0) ? d1 : (g == 1) ? d2 : d3;
    const float* w   = (g == 0) ? w1 : (g == 1) ? w2 : w3;
    int e = blockIdx.x * blockDim.x + threadIdx.x;
    if (e < EE) {
        int s = src[e], d = dst[e];
        float wv = w[e];
        atomicAdd(&g_degO[g * NN + s], wv);
        int pos = atomicAdd(&g_cur[g * NN + d], 1);
        g_csr[(g * NN + d) * CAP + pos] = make_int2(s, __float_as_int(wv));
    }
}

// ---------------- mm1: h1 = x @ W1  (N x 128)@(128 x 64) -> g_h4 ----------------
__global__ void k_mm1(const float* __restrict__ x, const float* __restrict__ W1) {
    __shared__ float ws[128 * 64];   // 32 KB
    __shared__ float xs[32 * 128];   // 16 KB
    int t = threadIdx.x;
    {
        const float4* W14 = (const float4*)W1;
        float4* ws4w = (float4*)ws;
        #pragma unroll
        for (int i = 0; i < 8; i++) ws4w[t + i * 256] = W14[t + i * 256];
    }
    const float4* ws4 = (const float4*)ws;
    int jg = t & 15;
    int r  = t >> 4;
    int row0 = blockIdx.x * 32;      // grid = 3125, exact
    {
        const float4* x4 = (const float4*)x;
        float4* xs4 = (float4*)xs;
        #pragma unroll
        for (int i = 0; i < 4; i++) {
            int idx = t + i * 256;
            xs4[idx] = x4[row0 * 32 + idx];
        }
    }
    __syncthreads();
    float4 a0 = make_float4(0.f, 0.f, 0.f, 0.f);
    float4 a1 = make_float4(0.f, 0.f, 0.f, 0.f);
    #pragma unroll 4
    for (int k = 0; k < 128; k++) {
        float  x0 = xs[r * 128 + k];
        float  x1 = xs[(r + 16) * 128 + k];
        float4 wv = ws4[k * 16 + jg];
        a0.x += x0 * wv.x; a0.y += x0 * wv.y; a0.z += x0 * wv.z; a0.w += x0 * wv.w;
        a1.x += x1 * wv.x; a1.y += x1 * wv.y; a1.z += x1 * wv.z; a1.w += x1 * wv.w;
    }
    g_h4[(row0 + r) * 16 + jg]      = a0;
    g_h4[(row0 + r + 16) * 16 + jg] = a1;
}

// ---------------- fused pull64 (g=0) + mm2: h2pre = (agg1/dw + b1) @ W2 -> g_t4 ------
// 512 threads = 16 warps; warp w owns row blockIdx.x*16 + w.
// Lane = ep*16 + fl: ep in {0,1} edge-parallel, fl in 0..15 feature float4.
__global__ void __launch_bounds__(512) k_pull64mm2(const float* __restrict__ b1,
                                                   const float* __restrict__ W2) {
    __shared__ float hs[16 * 64];    // 4 KB block tile of h1b
    __shared__ float ws[64 * 32];    // 8 KB W2
    int t = threadIdx.x;
    ((float4*)ws)[t] = ((const float4*)W2)[t];   // 512 float4 = 2048 floats
    int w  = t >> 5;
    int ln = t & 31;
    int ep = ln >> 4;                // 0..1
    int fl = ln & 15;                // 0..15
    int row = blockIdx.x * 16 + w;   // exact: 6250*16 = 100000
    int cnt = g_cur[row];
    int base = row * CAP;
    float4 acc = make_float4(0.f, 0.f, 0.f, 0.f);
    float dw = 0.f;
    #pragma unroll 4
    for (int j = ep; j < cnt; j += 2) {
        int2 e = __ldcs(&g_csr[base + j]);
        float n = __int_as_float(e.y) * rsqrtf(fmaxf(__ldg(&g_degO[e.x]), EPSI));
        float4 h = g_h4[e.x * 16 + fl];
        acc.x += h.x * n; acc.y += h.y * n;
        acc.z += h.z * n; acc.w += h.w * n;
        dw += n;
    }
    // reduce across ep (xor 16)
    acc.x += __shfl_xor_sync(0xffffffffu, acc.x, 16);
    acc.y += __shfl_xor_sync(0xffffffffu, acc.y, 16);
    acc.z += __shfl_xor_sync(0xffffffffu, acc.z, 16);
    acc.w += __shfl_xor_sync(0xffffffffu, acc.w, 16);
    dw    += __shfl_xor_sync(0xffffffffu, dw, 16);
    if (ep == 0) {
        float inv = 1.f / fmaxf(dw, EPSI);
        float4 bb = ((const float4*)b1)[fl];
        ((float4*)hs)[w * 16 + fl] = make_float4(acc.x * inv + bb.x, acc.y * inv + bb.y,
                                                 acc.z * inv + bb.z, acc.w * inv + bb.w);
    }
    __syncthreads();
    // mm2: 16x64 @ 64x32 -> 16x32; thread -> (r = t>>5, c = t&31)
    int r = t >> 5, c = t & 31;
    float s = 0.f;
    #pragma unroll
    for (int k = 0; k < 64; k++)
        s += hs[r * 64 + k] * ws[k * 32 + c];
    ((float*)g_t4)[(blockIdx.x * 16 + r) * 32 + c] = s;
}

// ---------------- pull32 layer 2 (g=1): h2b = agg2/dw + b2 : g_t4 -> g_h4 -----------
__global__ void __launch_bounds__(512) k_pull32L2(const float* __restrict__ b2) {
    int t = threadIdx.x;
    int w  = t >> 5;
    int ln = t & 31;
    int ep = ln >> 3;                // 0..3
    int fl = ln & 7;                 // 0..7
    int row = blockIdx.x * 16 + w;
    const float* degO = g_degO + NN;
    int cnt = g_cur[NN + row];
    int base = (NN + row) * CAP;
    float4 acc = make_float4(0.f, 0.f, 0.f, 0.f);
    float dw = 0.f;
    #pragma unroll 4
    for (int j = ep; j < cnt; j += 4) {
        int2 e = __ldcs(&g_csr[base + j]);
        float n = __int_as_float(e.y) * rsqrtf(fmaxf(__ldg(&degO[e.x]), EPSI));
        float4 h = g_t4[e.x * 8 + fl];
        acc.x += h.x * n; acc.y += h.y * n;
        acc.z += h.z * n; acc.w += h.w * n;
        dw += n;
    }
    acc.x += __shfl_xor_sync(0xffffffffu, acc.x, 8);
    acc.y += __shfl_xor_sync(0xffffffffu, acc.y, 8);
    acc.z += __shfl_xor_sync(0xffffffffu, acc.z, 8);
    acc.w += __shfl_xor_sync(0xffffffffu, acc.w, 8);
    dw    += __shfl_xor_sync(0xffffffffu, dw, 8);
    acc.x += __shfl_xor_sync(0xffffffffu, acc.x, 16);
    acc.y += __shfl_xor_sync(0xffffffffu, acc.y, 16);
    acc.z += __shfl_xor_sync(0xffffffffu, acc.z, 16);
    acc.w += __shfl_xor_sync(0xffffffffu, acc.w, 16);
    dw    += __shfl_xor_sync(0xffffffffu, dw, 16);
    if (ep == 0) {
        float inv = 1.f / fmaxf(dw, EPSI);
        float4 bb = ((const float4*)b2)[fl];
        g_h4[row * 8 + fl] = make_float4(acc.x * inv + bb.x, acc.y * inv + bb.y,
                                         acc.z * inv + bb.z, acc.w * inv + bb.w);
    }
}

// ---------------- fused pull32 layer 3 (g=2) + fin3: out = (agg3/dw) @ W3 + b3 ------
__global__ void __launch_bounds__(512) k_pull32fin3(const float* __restrict__ W3,
                                                    const float* __restrict__ b3,
                                                    float* __restrict__ out) {
    __shared__ float hs[16 * 32];    // 2 KB block tile of aggnorm3
    __shared__ float ws[32 * 32];    // 4 KB W3
    int t = threadIdx.x;
    if (t < 256) ((float4*)ws)[t] = ((const float4*)W3)[t];   // 256 float4 = 1024 floats
    int w  = t >> 5;
    int ln = t & 31;
    int ep = ln >> 3;
    int fl = ln & 7;
    int row = blockIdx.x * 16 + w;
    const float* degO = g_degO + 2 * NN;
    int cnt = g_cur[2 * NN + row];
    int base = (2 * NN + row) * CAP;
    float4 acc = make_float4(0.f, 0.f, 0.f, 0.f);
    float dw = 0.f;
    #pragma unroll 4
    for (int j = ep; j < cnt; j += 4) {
        int2 e = __ldcs(&g_csr[base + j]);
        float n = __int_as_float(e.y) * rsqrtf(fmaxf(__ldg(&degO[e.x]), EPSI));
        float4 h = g_h4[e.x * 8 + fl];
        acc.x += h.x * n; acc.y += h.y * n;
        acc.z += h.z * n; acc.w += h.w * n;
        dw += n;
    }
    acc.x += __shfl_xor_sync(0xffffffffu, acc.x, 8);
    acc.y += __shfl_xor_sync(0xffffffffu, acc.y, 8);
    acc.z += __shfl_xor_sync(0xffffffffu, acc.z, 8);
    acc.w += __shfl_xor_sync(0xffffffffu, acc.w, 8);
    dw    += __shfl_xor_sync(0xffffffffu, dw, 8);
    acc.x += __shfl_xor_sync(0xffffffffu, acc.x, 16);
    acc.y += __shfl_xor_sync(0xffffffffu, acc.y, 16);
    acc.z += __shfl_xor_sync(0xffffffffu, acc.z, 16);
    acc.w += __shfl_xor_sync(0xffffffffu, acc.w, 16);
    dw    += __shfl_xor_sync(0xffffffffu, dw, 16);
    if (ep == 0) {
        float inv = 1.f / fmaxf(dw, EPSI);
        ((float4*)hs)[w * 8 + fl] = make_float4(acc.x * inv, acc.y * inv,
                                                acc.z * inv, acc.w * inv);
    }
    __syncthreads();
    // fin3: 16x32 @ 32x32 + b3
    int r = t >> 5, c = t & 31;
    float s = 0.f;
    #pragma unroll
    for (int k = 0; k < 32; k++)
        s += hs[r * 32 + k] * ws[k * 32 + c];
    out[(blockIdx.x * 16 + r) * 32 + c] = s + b3[c];
}

// ---------------- launch ----------------
extern "C" void kernel_launch(void* const* d_in, const int* in_sizes, int n_in,
                              void* d_out, int out_size) {
    const float* x    = (const float*)d_in[0];
    const int*   src1 = (const int*)  d_in[1];
    const int*   dst1 = (const int*)  d_in[2];
    const float* w1   = (const float*)d_in[3];
    const int*   src2 = (const int*)  d_in[4];
    const int*   dst2 = (const int*)  d_in[5];
    const float* w2   = (const float*)d_in[6];
    const int*   src3 = (const int*)  d_in[7];
    const int*   dst3 = (const int*)  d_in[8];
    const float* w3   = (const float*)d_in[9];
    const float* W1   = (const float*)d_in[10];
    const float* b1   = (const float*)d_in[11];
    const float* W2   = (const float*)d_in[12];
    const float* b2   = (const float*)d_in[13];
    const float* W3   = (const float*)d_in[14];
    const float* b3   = (const float*)d_in[15];
    float* out = (float*)d_out;

    const int TB = 256;
    dim3 gE3((EE + TB - 1) / TB, 3);             // 6250 x 3 blocks, 1 edge/thread

    // slots arranged so ncu captures k_pull64mm2 (launch index 3)
    k_mm1<<<NN / 32, 256>>>(x, W1);                      // 0 (independent)
    k_zero<<<(3 * NN + TB - 1) / TB, TB>>>();            // 1
    k_fill3<<<gE3, TB>>>(src1, dst1, w1, src2, dst2, w2, src3, dst3, w3);   // 2
    k_pull64mm2<<<NN / 16, 512>>>(b1, W2);               // 3  <- captured
    k_pull32L2<<<NN / 16, 512>>>(b2);                    // 4
    k_pull32fin3<<<NN / 16, 512>>>(W3, b3, out);         // 5
}